// round 2
// baseline (speedup 1.0000x reference)
#include <cuda_runtime.h>
#include <cstdint>

#define BB 32
#define NN 512
#define FF 64
#define HH 8
#define ROWS (BB*NN)   // 16384

typedef unsigned long long ull;

// ---------------- scratch (static device globals; no allocation) ----------------
__device__ __align__(16) int16_t g_nbr[ROWS * NN];      // 16 MB neighbor lists
__device__              int      g_cnt[ROWS];
__device__ __align__(16) float   g_hp0[ROWS * FF];      // 4 MB
__device__ __align__(16) float   g_s0t[ROWS * HH];      // node-major [row][h]
__device__ __align__(16) float   g_d0t[ROWS * HH];
__device__ __align__(16) float   g_x1[ROWS * (HH*FF)];  // 32 MB (elu'd concat)
__device__ __align__(16) float   g_hp1[ROWS * FF];
__device__ __align__(16) float   g_s1t[ROWS * HH];
__device__ __align__(16) float   g_d1t[ROWS * HH];

// ---------------- packed f32x2 helpers ------------------------------------------
static __device__ __forceinline__ ull fma2(ull a, ull b, ull c) {
    ull r;
    asm("fma.rn.f32x2 %0, %1, %2, %3;" : "=l"(r) : "l"(a), "l"(b), "l"(c));
    return r;
}
static __device__ __forceinline__ ull pk2(float x, float y) {
    ull r;
    asm("mov.b64 %0, {%1, %2};" : "=l"(r) : "f"(x), "f"(y));
    return r;
}
static __device__ __forceinline__ void upk2(ull v, float& x, float& y) {
    asm("mov.b64 {%0, %1}, %2;" : "=f"(x), "=f"(y) : "l"(v));
}

// ---------------- kernel 1: compact adjacency rows into neighbor lists ----------
__global__ void __launch_bounds__(256) k_build_nbr(const float* __restrict__ adj) {
    const int row  = (blockIdx.x << 3) + (threadIdx.x >> 5);
    const int lane = threadIdx.x & 31;
    const int i    = row & (NN - 1);
    const float* arow = adj + ((size_t)row << 9);
    int16_t* outp = g_nbr + ((size_t)row << 9);
    int off = 0;
    #pragma unroll
    for (int base = 0; base < NN; base += 32) {
        const int j = base + lane;
        const bool p = (arow[j] != 0.f) || (j == i);   // diag forced to 1
        const unsigned msk = __ballot_sync(0xffffffffu, p);
        if (p) outp[off + __popc(msk & ((1u << lane) - 1u))] = (int16_t)j;
        off += __popc(msk);
    }
    if (lane == 0) g_cnt[row] = off;
}

// ---------------- kernel 2: GEMM  C[M,64] = A[M,K] @ B[K,64]  -------------------
template<int K, int LAYER>
__global__ void __launch_bounds__(256) k_gemm(const float* __restrict__ Aext,
                                              const float* __restrict__ Bw) {
    const float* __restrict__ A = (LAYER == 0) ? Aext : g_x1;
    float* __restrict__ C = (LAYER == 0) ? g_hp0 : g_hp1;
    __shared__ float As[32][72];   // As[kk][m] (transposed)
    __shared__ float Bs[32][72];   // Bs[kk][n]
    const int bm = blockIdx.x << 6;
    const int t  = threadIdx.x;
    const int ty = t >> 4, tx = t & 15;
    ull acc[4][2];
    #pragma unroll
    for (int r = 0; r < 4; r++) { acc[r][0] = 0ull; acc[r][1] = 0ull; }

    for (int k0 = 0; k0 < K; k0 += 32) {
        #pragma unroll
        for (int l = 0; l < 2; l++) {
            const int idx = t + (l << 8);          // 0..511
            const int m  = idx >> 3;
            const int kq = (idx & 7) << 2;
            float4 av = *(const float4*)(A + (size_t)(bm + m) * K + k0 + kq);
            As[kq + 0][m] = av.x; As[kq + 1][m] = av.y;
            As[kq + 2][m] = av.z; As[kq + 3][m] = av.w;
            const int kk = idx >> 4;
            const int nq = (idx & 15) << 2;
            *(float4*)&Bs[kk][nq] = *(const float4*)(Bw + (size_t)(k0 + kk) * 64 + nq);
        }
        __syncthreads();
        #pragma unroll
        for (int kk = 0; kk < 32; kk++) {
            const float4 a = *(const float4*)&As[kk][ty << 2];
            const longlong2 bv = *(const longlong2*)&Bs[kk][tx << 2];
            const ull b0 = (ull)bv.x;
            const ull b1 = (ull)bv.y;
            const ull a0 = pk2(a.x, a.x), a1 = pk2(a.y, a.y);
            const ull a2 = pk2(a.z, a.z), a3 = pk2(a.w, a.w);
            acc[0][0] = fma2(a0, b0, acc[0][0]); acc[0][1] = fma2(a0, b1, acc[0][1]);
            acc[1][0] = fma2(a1, b0, acc[1][0]); acc[1][1] = fma2(a1, b1, acc[1][1]);
            acc[2][0] = fma2(a2, b0, acc[2][0]); acc[2][1] = fma2(a2, b1, acc[2][1]);
            acc[3][0] = fma2(a3, b0, acc[3][0]); acc[3][1] = fma2(a3, b1, acc[3][1]);
        }
        __syncthreads();
    }
    #pragma unroll
    for (int r = 0; r < 4; r++) {
        float o0, o1, o2, o3;
        upk2(acc[r][0], o0, o1); upk2(acc[r][1], o2, o3);
        *(float4*)(C + (size_t)(bm + (ty << 2) + r) * 64 + (tx << 2)) =
            make_float4(o0, o1, o2, o3);
    }
}

// ---------------- kernel 3: s/d projections, stored NODE-MAJOR [row][h] ---------
template<int LAYER>
__global__ void __launch_bounds__(256) k_sd(const float* __restrict__ asrc,
                                            const float* __restrict__ adst) {
    const float* __restrict__ hp = (LAYER == 0) ? g_hp0 : g_hp1;
    float* __restrict__ s = (LAYER == 0) ? g_s0t : g_s1t;
    float* __restrict__ d = (LAYER == 0) ? g_d0t : g_d1t;
    const int row  = (blockIdx.x << 3) + (threadIdx.x >> 5);
    const int lane = threadIdx.x & 31;
    const float h0 = hp[(size_t)row * 64 + lane];
    const float h1 = hp[(size_t)row * 64 + 32 + lane];
    float ps[8], pd[8];
    #pragma unroll
    for (int h = 0; h < 8; h++) {
        ps[h] = h0 * asrc[(lane << 3) + h] + h1 * asrc[((lane + 32) << 3) + h];
        pd[h] = h0 * adst[(lane << 3) + h] + h1 * adst[((lane + 32) << 3) + h];
    }
    #pragma unroll
    for (int h = 0; h < 8; h++) {
        #pragma unroll
        for (int o = 16; o; o >>= 1) {
            ps[h] += __shfl_xor_sync(0xffffffffu, ps[h], o);
            pd[h] += __shfl_xor_sync(0xffffffffu, pd[h], o);
        }
    }
    if (lane == 0) {
        *(float4*)(s + (row << 3))     = make_float4(ps[0], ps[1], ps[2], ps[3]);
        *(float4*)(s + (row << 3) + 4) = make_float4(ps[4], ps[5], ps[6], ps[7]);
        *(float4*)(d + (row << 3))     = make_float4(pd[0], pd[1], pd[2], pd[3]);
        *(float4*)(d + (row << 3) + 4) = make_float4(pd[4], pd[5], pd[6], pd[7]);
    }
}

// online (m, Z) update for one candidate lv (masked entries skipped)
static __device__ __forceinline__ void onl_upd(float lv, float& m, float& Z) {
    if (lv != 0.f) {
        const float mn = fmaxf(m, lv);
        Z = Z * __expf(m - mn) + __expf(lv - mn);
        m = mn;
    }
}

// ---------------- kernel 4: layer-1 sparse softmax + 8-head aggregate + elu -----
__global__ void __launch_bounds__(128) k_agg1() {
    __shared__ __align__(16) float2 s_w[4][32][8];   // chunk weights, pre-dup {w,w}
    __shared__ int    s_j[4][32];
    const int w = threadIdx.x >> 5, lane = threadIdx.x & 31;
    const int row = (blockIdx.x << 2) + w;
    const int b = row >> 9;
    const int cnt = g_cnt[row];
    const int16_t* __restrict__ nbrrow = g_nbr + ((size_t)row << 9);
    const float* __restrict__ dtb  = g_d0t + ((size_t)b << 12);   // [i][h]
    const float* __restrict__ hp0b = g_hp0 + ((size_t)b << 15);

    float sh[8], m[8], Z[8];
    {
        const float4 s0 = *(const float4*)(g_s0t + (row << 3));
        const float4 s1 = *(const float4*)(g_s0t + (row << 3) + 4);
        sh[0] = s0.x; sh[1] = s0.y; sh[2] = s0.z; sh[3] = s0.w;
        sh[4] = s1.x; sh[5] = s1.y; sh[6] = s1.z; sh[7] = s1.w;
    }
    #pragma unroll
    for (int h = 0; h < 8; h++) { m[h] = -3.402823466e38f; Z[h] = 0.f; }

    // single online sweep: per-lane (m, Z) for its neighbors
    for (int p = lane; p < cnt; p += 32) {
        const int j = (int)nbrrow[p];
        const float4 da = *(const float4*)(dtb + (j << 3));
        const float4 db = *(const float4*)(dtb + (j << 3) + 4);
        float dv[8] = {da.x, da.y, da.z, da.w, db.x, db.y, db.z, db.w};
        #pragma unroll
        for (int h = 0; h < 8; h++) {
            const float ev = sh[h] + dv[h];
            const float lv = ev >= 0.f ? ev : 0.2f * ev;
            onl_upd(lv, m[h], Z[h]);
        }
    }
    // butterfly combine of (m, Z) pairs
    #pragma unroll
    for (int o = 16; o; o >>= 1) {
        #pragma unroll
        for (int h = 0; h < 8; h++) {
            const float m2 = __shfl_xor_sync(0xffffffffu, m[h], o);
            const float Z2 = __shfl_xor_sync(0xffffffffu, Z[h], o);
            const float mn = fmaxf(m[h], m2);
            Z[h] = Z[h] * __expf(m[h] - mn) + Z2 * __expf(m2 - mn);
            m[h] = mn;
        }
    }
    float rz[8];
    #pragma unroll
    for (int h = 0; h < 8; h++) rz[h] = 1.f / Z[h];

    ull acc[8];
    #pragma unroll
    for (int h = 0; h < 8; h++) acc[h] = 0ull;

    for (int base = 0; base < cnt; base += 32) {
        const int nc = min(32, cnt - base);
        if (lane < nc) {
            const int j = (int)nbrrow[base + lane];
            const float4 da = *(const float4*)(dtb + (j << 3));
            const float4 db = *(const float4*)(dtb + (j << 3) + 4);
            float dv[8] = {da.x, da.y, da.z, da.w, db.x, db.y, db.z, db.w};
            float wt[8];
            #pragma unroll
            for (int h = 0; h < 8; h++) {
                const float ev = sh[h] + dv[h];
                const float lv = ev >= 0.f ? ev : 0.2f * ev;
                wt[h] = (lv != 0.f) ? __expf(lv - m[h]) * rz[h] : 0.f;
            }
            float4* wp = (float4*)&s_w[w][lane][0];
            wp[0] = make_float4(wt[0], wt[0], wt[1], wt[1]);
            wp[1] = make_float4(wt[2], wt[2], wt[3], wt[3]);
            wp[2] = make_float4(wt[4], wt[4], wt[5], wt[5]);
            wp[3] = make_float4(wt[6], wt[6], wt[7], wt[7]);
            s_j[w][lane] = j;
        }
        __syncwarp();
        #pragma unroll 4
        for (int q = 0; q < nc; q++) {
            const int j = s_j[w][q];
            const ull hpv = ((const ull*)(hp0b + ((size_t)j << 6)))[lane];
            const longlong2* wp2 = (const longlong2*)&s_w[w][q][0];
            const longlong2 w01 = wp2[0], w23 = wp2[1], w45 = wp2[2], w67 = wp2[3];
            acc[0] = fma2((ull)w01.x, hpv, acc[0]);
            acc[1] = fma2((ull)w01.y, hpv, acc[1]);
            acc[2] = fma2((ull)w23.x, hpv, acc[2]);
            acc[3] = fma2((ull)w23.y, hpv, acc[3]);
            acc[4] = fma2((ull)w45.x, hpv, acc[4]);
            acc[5] = fma2((ull)w45.y, hpv, acc[5]);
            acc[6] = fma2((ull)w67.x, hpv, acc[6]);
            acc[7] = fma2((ull)w67.y, hpv, acc[7]);
        }
        __syncwarp();
    }
    // write x1 = elu(concat heads)
    float* xout = g_x1 + ((size_t)row << 9);
    #pragma unroll
    for (int h = 0; h < 8; h++) {
        float xf, yf; upk2(acc[h], xf, yf);
        xf = xf > 0.f ? xf : expm1f(xf);
        yf = yf > 0.f ? yf : expm1f(yf);
        ((float2*)(xout + (h << 6)))[lane] = make_float2(xf, yf);
    }
}

// ---------------- kernel 5: layer-2 aggregate, head-mean folded into weights ----
__global__ void __launch_bounds__(128) k_agg2(float* __restrict__ out) {
    __shared__ __align__(16) float2 s_wb[4][32];
    __shared__ int    s_j[4][32];
    const int w = threadIdx.x >> 5, lane = threadIdx.x & 31;
    const int row = (blockIdx.x << 2) + w;
    const int b = row >> 9;
    const int cnt = g_cnt[row];
    const int16_t* __restrict__ nbrrow = g_nbr + ((size_t)row << 9);
    const float* __restrict__ dtb  = g_d1t + ((size_t)b << 12);
    const float* __restrict__ hp1b = g_hp1 + ((size_t)b << 15);

    float sh[8], m[8], Z[8];
    {
        const float4 s0 = *(const float4*)(g_s1t + (row << 3));
        const float4 s1 = *(const float4*)(g_s1t + (row << 3) + 4);
        sh[0] = s0.x; sh[1] = s0.y; sh[2] = s0.z; sh[3] = s0.w;
        sh[4] = s1.x; sh[5] = s1.y; sh[6] = s1.z; sh[7] = s1.w;
    }
    #pragma unroll
    for (int h = 0; h < 8; h++) { m[h] = -3.402823466e38f; Z[h] = 0.f; }

    for (int p = lane; p < cnt; p += 32) {
        const int j = (int)nbrrow[p];
        const float4 da = *(const float4*)(dtb + (j << 3));
        const float4 db = *(const float4*)(dtb + (j << 3) + 4);
        float dv[8] = {da.x, da.y, da.z, da.w, db.x, db.y, db.z, db.w};
        #pragma unroll
        for (int h = 0; h < 8; h++) {
            const float ev = sh[h] + dv[h];
            const float lv = ev >= 0.f ? ev : 0.2f * ev;
            onl_upd(lv, m[h], Z[h]);
        }
    }
    #pragma unroll
    for (int o = 16; o; o >>= 1) {
        #pragma unroll
        for (int h = 0; h < 8; h++) {
            const float m2 = __shfl_xor_sync(0xffffffffu, m[h], o);
            const float Z2 = __shfl_xor_sync(0xffffffffu, Z[h], o);
            const float mn = fmaxf(m[h], m2);
            Z[h] = Z[h] * __expf(m[h] - mn) + Z2 * __expf(m2 - mn);
            m[h] = mn;
        }
    }
    float rz[8];
    #pragma unroll
    for (int h = 0; h < 8; h++) rz[h] = 1.f / Z[h];

    ull acc = 0ull;
    for (int base = 0; base < cnt; base += 32) {
        const int nc = min(32, cnt - base);
        if (lane < nc) {
            const int j = (int)nbrrow[base + lane];
            const float4 da = *(const float4*)(dtb + (j << 3));
            const float4 db = *(const float4*)(dtb + (j << 3) + 4);
            float dv[8] = {da.x, da.y, da.z, da.w, db.x, db.y, db.z, db.w};
            float ws = 0.f;
            #pragma unroll
            for (int h = 0; h < 8; h++) {
                const float ev = sh[h] + dv[h];
                const float lv = ev >= 0.f ? ev : 0.2f * ev;
                if (lv != 0.f) ws += __expf(lv - m[h]) * rz[h];
            }
            ws *= 0.125f;                       // mean over heads
            s_wb[w][lane] = make_float2(ws, ws);
            s_j[w][lane]  = (int)j;
        }
        __syncwarp();
        #pragma unroll 4
        for (int q = 0; q < nc; q++) {
            const int j = s_j[w][q];
            const ull hpv = ((const ull*)(hp1b + ((size_t)j << 6)))[lane];
            const ull wv = *(const ull*)&s_wb[w][q];
            acc = fma2(wv, hpv, acc);
        }
        __syncwarp();
    }
    float xf, yf; upk2(acc, xf, yf);
    ((float2*)(out + ((size_t)row << 6)))[lane] = make_float2(xf, yf);
}

// ---------------- launch --------------------------------------------------------
extern "C" void kernel_launch(void* const* d_in, const int* in_sizes, int n_in,
                              void* d_out, int out_size) {
    const float* x     = (const float*)d_in[0];
    const float* adj   = (const float*)d_in[1];
    const float* W0    = (const float*)d_in[4];
    const float* asrc0 = (const float*)d_in[5];
    const float* adst0 = (const float*)d_in[6];
    const float* W1    = (const float*)d_in[7];
    const float* asrc1 = (const float*)d_in[8];
    const float* adst1 = (const float*)d_in[9];
    float* out = (float*)d_out;

    k_build_nbr<<<ROWS / 8, 256>>>(adj);
    k_gemm<64, 0><<<ROWS / 64, 256>>>(x, W0);
    k_sd<0><<<ROWS / 8, 256>>>(asrc0, adst0);
    k_agg1<<<ROWS / 4, 128>>>();
    k_gemm<512, 1><<<ROWS / 64, 256>>>(nullptr, W1);
    k_sd<1><<<ROWS / 8, 256>>>(asrc1, adst1);
    k_agg2<<<ROWS / 4, 128>>>(out);
}

// round 3
// speedup vs baseline: 1.0450x; 1.0450x over previous
#include <cuda_runtime.h>
#include <cstdint>

#define BB 32
#define NN 512
#define FF 64
#define HH 8
#define ROWS (BB*NN)   // 16384

typedef unsigned long long ull;

// ---------------- scratch (static device globals; no allocation) ----------------
__device__ __align__(16) int16_t g_nbr[ROWS * NN];      // 16 MB neighbor lists
__device__              int      g_cnt[ROWS];
__device__ __align__(16) float   g_hp0[ROWS * FF];      // 4 MB
__device__ __align__(16) float   g_s0t[ROWS * HH];      // node-major [row][h]
__device__ __align__(16) float   g_d0t[ROWS * HH];
__device__ __align__(16) float   g_x1[ROWS * (HH*FF)];  // 32 MB (elu'd concat)
__device__ __align__(16) float   g_hp1[ROWS * FF];
__device__ __align__(16) float   g_s1t[ROWS * HH];
__device__ __align__(16) float   g_d1t[ROWS * HH];

// ---------------- packed f32x2 helpers ------------------------------------------
static __device__ __forceinline__ ull fma2(ull a, ull b, ull c) {
    ull r;
    asm("fma.rn.f32x2 %0, %1, %2, %3;" : "=l"(r) : "l"(a), "l"(b), "l"(c));
    return r;
}
static __device__ __forceinline__ ull pk2(float x, float y) {
    ull r;
    asm("mov.b64 %0, {%1, %2};" : "=l"(r) : "f"(x), "f"(y));
    return r;
}
static __device__ __forceinline__ void upk2(ull v, float& x, float& y) {
    asm("mov.b64 {%0, %1}, %2;" : "=f"(x), "=f"(y) : "l"(v));
}

// ---------------- kernel 1: compact adjacency rows into neighbor lists ----------
__global__ void __launch_bounds__(256) k_build_nbr(const float* __restrict__ adj) {
    const int row  = (blockIdx.x << 3) + (threadIdx.x >> 5);
    const int lane = threadIdx.x & 31;
    const int i    = row & (NN - 1);
    const float* arow = adj + ((size_t)row << 9);
    int16_t* outp = g_nbr + ((size_t)row << 9);
    int off = 0;
    #pragma unroll
    for (int base = 0; base < NN; base += 32) {
        const int j = base + lane;
        const bool p = (arow[j] != 0.f) || (j == i);   // diag forced to 1
        const unsigned msk = __ballot_sync(0xffffffffu, p);
        if (p) outp[off + __popc(msk & ((1u << lane) - 1u))] = (int16_t)j;
        off += __popc(msk);
    }
    if (lane == 0) g_cnt[row] = off;
}

// ---------------- kernel 2: GEMM  C[M,64] = A[M,K] @ B[K,64]  -------------------
template<int K, int LAYER>
__global__ void __launch_bounds__(256) k_gemm(const float* __restrict__ Aext,
                                              const float* __restrict__ Bw) {
    const float* __restrict__ A = (LAYER == 0) ? Aext : g_x1;
    float* __restrict__ C = (LAYER == 0) ? g_hp0 : g_hp1;
    __shared__ float As[32][72];   // As[kk][m] (transposed)
    __shared__ float Bs[32][72];   // Bs[kk][n]
    const int bm = blockIdx.x << 6;
    const int t  = threadIdx.x;
    const int ty = t >> 4, tx = t & 15;
    ull acc[4][2];
    #pragma unroll
    for (int r = 0; r < 4; r++) { acc[r][0] = 0ull; acc[r][1] = 0ull; }

    for (int k0 = 0; k0 < K; k0 += 32) {
        #pragma unroll
        for (int l = 0; l < 2; l++) {
            const int idx = t + (l << 8);          // 0..511
            const int m  = idx >> 3;
            const int kq = (idx & 7) << 2;
            float4 av = *(const float4*)(A + (size_t)(bm + m) * K + k0 + kq);
            As[kq + 0][m] = av.x; As[kq + 1][m] = av.y;
            As[kq + 2][m] = av.z; As[kq + 3][m] = av.w;
            const int kk = idx >> 4;
            const int nq = (idx & 15) << 2;
            *(float4*)&Bs[kk][nq] = *(const float4*)(Bw + (size_t)(k0 + kk) * 64 + nq);
        }
        __syncthreads();
        #pragma unroll
        for (int kk = 0; kk < 32; kk++) {
            const float4 a = *(const float4*)&As[kk][ty << 2];
            const longlong2 bv = *(const longlong2*)&Bs[kk][tx << 2];
            const ull b0 = (ull)bv.x;
            const ull b1 = (ull)bv.y;
            const ull a0 = pk2(a.x, a.x), a1 = pk2(a.y, a.y);
            const ull a2 = pk2(a.z, a.z), a3 = pk2(a.w, a.w);
            acc[0][0] = fma2(a0, b0, acc[0][0]); acc[0][1] = fma2(a0, b1, acc[0][1]);
            acc[1][0] = fma2(a1, b0, acc[1][0]); acc[1][1] = fma2(a1, b1, acc[1][1]);
            acc[2][0] = fma2(a2, b0, acc[2][0]); acc[2][1] = fma2(a2, b1, acc[2][1]);
            acc[3][0] = fma2(a3, b0, acc[3][0]); acc[3][1] = fma2(a3, b1, acc[3][1]);
        }
        __syncthreads();
    }
    #pragma unroll
    for (int r = 0; r < 4; r++) {
        float o0, o1, o2, o3;
        upk2(acc[r][0], o0, o1); upk2(acc[r][1], o2, o3);
        *(float4*)(C + (size_t)(bm + (ty << 2) + r) * 64 + (tx << 2)) =
            make_float4(o0, o1, o2, o3);
    }
}

// ---------------- kernel 3: s/d projections, stored NODE-MAJOR [row][h] ---------
template<int LAYER>
__global__ void __launch_bounds__(256) k_sd(const float* __restrict__ asrc,
                                            const float* __restrict__ adst) {
    const float* __restrict__ hp = (LAYER == 0) ? g_hp0 : g_hp1;
    float* __restrict__ s = (LAYER == 0) ? g_s0t : g_s1t;
    float* __restrict__ d = (LAYER == 0) ? g_d0t : g_d1t;
    const int row  = (blockIdx.x << 3) + (threadIdx.x >> 5);
    const int lane = threadIdx.x & 31;
    const float h0 = hp[(size_t)row * 64 + lane];
    const float h1 = hp[(size_t)row * 64 + 32 + lane];
    float ps[8], pd[8];
    #pragma unroll
    for (int h = 0; h < 8; h++) {
        ps[h] = h0 * asrc[(lane << 3) + h] + h1 * asrc[((lane + 32) << 3) + h];
        pd[h] = h0 * adst[(lane << 3) + h] + h1 * adst[((lane + 32) << 3) + h];
    }
    #pragma unroll
    for (int h = 0; h < 8; h++) {
        #pragma unroll
        for (int o = 16; o; o >>= 1) {
            ps[h] += __shfl_xor_sync(0xffffffffu, ps[h], o);
            pd[h] += __shfl_xor_sync(0xffffffffu, pd[h], o);
        }
    }
    if (lane == 0) {
        *(float4*)(s + (row << 3))     = make_float4(ps[0], ps[1], ps[2], ps[3]);
        *(float4*)(s + (row << 3) + 4) = make_float4(ps[4], ps[5], ps[6], ps[7]);
        *(float4*)(d + (row << 3))     = make_float4(pd[0], pd[1], pd[2], pd[3]);
        *(float4*)(d + (row << 3) + 4) = make_float4(pd[4], pd[5], pd[6], pd[7]);
    }
}

// online (m, Z) update for one candidate lv (masked entries skipped)
static __device__ __forceinline__ void onl_upd(float lv, float& m, float& Z) {
    if (lv != 0.f) {
        const float mn = fmaxf(m, lv);
        Z = Z * __expf(m - mn) + __expf(lv - mn);
        m = mn;
    }
}

// ---------------- kernel 4: layer-1 sparse softmax + 8-head aggregate + elu -----
// Latency fix: per 32-neighbor chunk, the 64B hp rows for 16 neighbors are
// preloaded into registers back-to-back (MLP=16) before the FMA phase consumes
// them. Neighbor index is broadcast from the weight-phase lane via SHFL.
__global__ void __launch_bounds__(128) k_agg1() {
    __shared__ __align__(16) float2 s_w[4][32][8];   // chunk weights, pre-dup {w,w}
    const int w = threadIdx.x >> 5, lane = threadIdx.x & 31;
    const int row = (blockIdx.x << 2) + w;
    const int b = row >> 9, i = row & (NN - 1);
    const int cnt = g_cnt[row];
    const int16_t* __restrict__ nbrrow = g_nbr + ((size_t)row << 9);
    const float* __restrict__ dtb  = g_d0t + ((size_t)b << 12);   // [i][h]
    const float* __restrict__ hp0b = g_hp0 + ((size_t)b << 15);

    float sh[8], m[8], Z[8];
    {
        const float4 s0 = *(const float4*)(g_s0t + (row << 3));
        const float4 s1 = *(const float4*)(g_s0t + (row << 3) + 4);
        sh[0] = s0.x; sh[1] = s0.y; sh[2] = s0.z; sh[3] = s0.w;
        sh[4] = s1.x; sh[5] = s1.y; sh[6] = s1.z; sh[7] = s1.w;
    }
    #pragma unroll
    for (int h = 0; h < 8; h++) { m[h] = -3.402823466e38f; Z[h] = 0.f; }

    // single online sweep: per-lane (m, Z)
    for (int p = lane; p < cnt; p += 32) {
        const int j = (int)nbrrow[p];
        const float4 da = *(const float4*)(dtb + (j << 3));
        const float4 db = *(const float4*)(dtb + (j << 3) + 4);
        float dv[8] = {da.x, da.y, da.z, da.w, db.x, db.y, db.z, db.w};
        #pragma unroll
        for (int h = 0; h < 8; h++) {
            const float ev = sh[h] + dv[h];
            const float lv = ev >= 0.f ? ev : 0.2f * ev;
            onl_upd(lv, m[h], Z[h]);
        }
    }
    // butterfly combine of (m, Z) pairs
    #pragma unroll
    for (int o = 16; o; o >>= 1) {
        #pragma unroll
        for (int h = 0; h < 8; h++) {
            const float m2 = __shfl_xor_sync(0xffffffffu, m[h], o);
            const float Z2 = __shfl_xor_sync(0xffffffffu, Z[h], o);
            const float mn = fmaxf(m[h], m2);
            Z[h] = Z[h] * __expf(m[h] - mn) + Z2 * __expf(m2 - mn);
            m[h] = mn;
        }
    }
    float rz[8];
    #pragma unroll
    for (int h = 0; h < 8; h++) rz[h] = 1.f / Z[h];

    ull acc[8];
    #pragma unroll
    for (int h = 0; h < 8; h++) acc[h] = 0ull;

    for (int base = 0; base < cnt; base += 32) {
        const int nc = min(32, cnt - base);
        // weight phase: lane <-> neighbor; pad with zero-weight self loops
        int jm = i;
        float wt[8];
        #pragma unroll
        for (int h = 0; h < 8; h++) wt[h] = 0.f;
        if (lane < nc) {
            jm = (int)nbrrow[base + lane];
            const float4 da = *(const float4*)(dtb + (jm << 3));
            const float4 db = *(const float4*)(dtb + (jm << 3) + 4);
            float dv[8] = {da.x, da.y, da.z, da.w, db.x, db.y, db.z, db.w};
            #pragma unroll
            for (int h = 0; h < 8; h++) {
                const float ev = sh[h] + dv[h];
                const float lv = ev >= 0.f ? ev : 0.2f * ev;
                wt[h] = (lv != 0.f) ? __expf(lv - m[h]) * rz[h] : 0.f;
            }
        }
        {
            float4* wp = (float4*)&s_w[w][lane][0];
            wp[0] = make_float4(wt[0], wt[0], wt[1], wt[1]);
            wp[1] = make_float4(wt[2], wt[2], wt[3], wt[3]);
            wp[2] = make_float4(wt[4], wt[4], wt[5], wt[5]);
            wp[3] = make_float4(wt[6], wt[6], wt[7], wt[7]);
        }
        __syncwarp();
        // two software-pipelined half-chunks of 16
        #pragma unroll
        for (int half = 0; half < 2; half++) {
            if (half == 1 && nc <= 16) break;
            ull hpv[16];
            #pragma unroll
            for (int q = 0; q < 16; q++) {
                const int j = __shfl_sync(0xffffffffu, jm, (half << 4) + q);
                hpv[q] = ((const ull*)(hp0b + ((size_t)j << 6)))[lane];
            }
            #pragma unroll
            for (int q = 0; q < 16; q++) {
                const longlong2* wp2 = (const longlong2*)&s_w[w][(half << 4) + q][0];
                const longlong2 w01 = wp2[0], w23 = wp2[1], w45 = wp2[2], w67 = wp2[3];
                acc[0] = fma2((ull)w01.x, hpv[q], acc[0]);
                acc[1] = fma2((ull)w01.y, hpv[q], acc[1]);
                acc[2] = fma2((ull)w23.x, hpv[q], acc[2]);
                acc[3] = fma2((ull)w23.y, hpv[q], acc[3]);
                acc[4] = fma2((ull)w45.x, hpv[q], acc[4]);
                acc[5] = fma2((ull)w45.y, hpv[q], acc[5]);
                acc[6] = fma2((ull)w67.x, hpv[q], acc[6]);
                acc[7] = fma2((ull)w67.y, hpv[q], acc[7]);
            }
        }
        __syncwarp();
    }
    // write x1 = elu(concat heads)
    float* xout = g_x1 + ((size_t)row << 9);
    #pragma unroll
    for (int h = 0; h < 8; h++) {
        float xf, yf; upk2(acc[h], xf, yf);
        xf = xf > 0.f ? xf : expm1f(xf);
        yf = yf > 0.f ? yf : expm1f(yf);
        ((float2*)(xout + (h << 6)))[lane] = make_float2(xf, yf);
    }
}

// ---------------- kernel 5: layer-2 aggregate, head-mean folded into weights ----
__global__ void __launch_bounds__(128) k_agg2(float* __restrict__ out) {
    __shared__ __align__(16) float2 s_wb[4][32];
    const int w = threadIdx.x >> 5, lane = threadIdx.x & 31;
    const int row = (blockIdx.x << 2) + w;
    const int b = row >> 9, i = row & (NN - 1);
    const int cnt = g_cnt[row];
    const int16_t* __restrict__ nbrrow = g_nbr + ((size_t)row << 9);
    const float* __restrict__ dtb  = g_d1t + ((size_t)b << 12);
    const float* __restrict__ hp1b = g_hp1 + ((size_t)b << 15);

    float sh[8], m[8], Z[8];
    {
        const float4 s0 = *(const float4*)(g_s1t + (row << 3));
        const float4 s1 = *(const float4*)(g_s1t + (row << 3) + 4);
        sh[0] = s0.x; sh[1] = s0.y; sh[2] = s0.z; sh[3] = s0.w;
        sh[4] = s1.x; sh[5] = s1.y; sh[6] = s1.z; sh[7] = s1.w;
    }
    #pragma unroll
    for (int h = 0; h < 8; h++) { m[h] = -3.402823466e38f; Z[h] = 0.f; }

    for (int p = lane; p < cnt; p += 32) {
        const int j = (int)nbrrow[p];
        const float4 da = *(const float4*)(dtb + (j << 3));
        const float4 db = *(const float4*)(dtb + (j << 3) + 4);
        float dv[8] = {da.x, da.y, da.z, da.w, db.x, db.y, db.z, db.w};
        #pragma unroll
        for (int h = 0; h < 8; h++) {
            const float ev = sh[h] + dv[h];
            const float lv = ev >= 0.f ? ev : 0.2f * ev;
            onl_upd(lv, m[h], Z[h]);
        }
    }
    #pragma unroll
    for (int o = 16; o; o >>= 1) {
        #pragma unroll
        for (int h = 0; h < 8; h++) {
            const float m2 = __shfl_xor_sync(0xffffffffu, m[h], o);
            const float Z2 = __shfl_xor_sync(0xffffffffu, Z[h], o);
            const float mn = fmaxf(m[h], m2);
            Z[h] = Z[h] * __expf(m[h] - mn) + Z2 * __expf(m2 - mn);
            m[h] = mn;
        }
    }
    float rz[8];
    #pragma unroll
    for (int h = 0; h < 8; h++) rz[h] = 1.f / Z[h];

    ull acc = 0ull;
    for (int base = 0; base < cnt; base += 32) {
        const int nc = min(32, cnt - base);
        int jm = i;
        float ws = 0.f;
        if (lane < nc) {
            jm = (int)nbrrow[base + lane];
            const float4 da = *(const float4*)(dtb + (jm << 3));
            const float4 db = *(const float4*)(dtb + (jm << 3) + 4);
            float dv[8] = {da.x, da.y, da.z, da.w, db.x, db.y, db.z, db.w};
            #pragma unroll
            for (int h = 0; h < 8; h++) {
                const float ev = sh[h] + dv[h];
                const float lv = ev >= 0.f ? ev : 0.2f * ev;
                if (lv != 0.f) ws += __expf(lv - m[h]) * rz[h];
            }
            ws *= 0.125f;                       // mean over heads
        }
        s_wb[w][lane] = make_float2(ws, ws);
        __syncwarp();
        #pragma unroll
        for (int half = 0; half < 2; half++) {
            if (half == 1 && nc <= 16) break;
            ull hpv[16];
            #pragma unroll
            for (int q = 0; q < 16; q++) {
                const int j = __shfl_sync(0xffffffffu, jm, (half << 4) + q);
                hpv[q] = ((const ull*)(hp1b + ((size_t)j << 6)))[lane];
            }
            #pragma unroll
            for (int q = 0; q < 16; q++) {
                const ull wv = *(const ull*)&s_wb[w][(half << 4) + q];
                acc = fma2(wv, hpv[q], acc);
            }
        }
        __syncwarp();
    }
    float xf, yf; upk2(acc, xf, yf);
    ((float2*)(out + ((size_t)row << 6)))[lane] = make_float2(xf, yf);
}

// ---------------- launch --------------------------------------------------------
extern "C" void kernel_launch(void* const* d_in, const int* in_sizes, int n_in,
                              void* d_out, int out_size) {
    const float* x     = (const float*)d_in[0];
    const float* adj   = (const float*)d_in[1];
    const float* W0    = (const float*)d_in[4];
    const float* asrc0 = (const float*)d_in[5];
    const float* adst0 = (const float*)d_in[6];
    const float* W1    = (const float*)d_in[7];
    const float* asrc1 = (const float*)d_in[8];
    const float* adst1 = (const float*)d_in[9];
    float* out = (float*)d_out;

    k_build_nbr<<<ROWS / 8, 256>>>(adj);
    k_gemm<64, 0><<<ROWS / 64, 256>>>(x, W0);
    k_sd<0><<<ROWS / 8, 256>>>(asrc0, adst0);
    k_agg1<<<ROWS / 4, 128>>>();
    k_gemm<512, 1><<<ROWS / 64, 256>>>(nullptr, W1);
    k_sd<1><<<ROWS / 8, 256>>>(asrc1, adst1);
    k_agg2<<<ROWS / 4, 128>>>(out);
}

// round 4
// speedup vs baseline: 1.2191x; 1.1666x over previous
#include <cuda_runtime.h>
#include <cstdint>

#define BB 32
#define NN 512
#define FF 64
#define HH 8
#define ROWS (BB*NN)   // 16384

typedef unsigned long long ull;

// ---------------- scratch (static device globals; no allocation) ----------------
__device__ __align__(16) int16_t g_nbr[ROWS * NN];      // 16 MB neighbor lists
__device__              int      g_cnt[ROWS];
__device__ __align__(16) float   g_hp0[ROWS * FF];      // 4 MB
__device__ __align__(16) float   g_s0t[ROWS * HH];      // node-major [row][h]
__device__ __align__(16) float   g_d0t[ROWS * HH];
__device__ __align__(16) float   g_x1[ROWS * (HH*FF)];  // 32 MB (elu'd concat)
__device__ __align__(16) float   g_hp1[ROWS * FF];
__device__ __align__(16) float   g_s1t[ROWS * HH];
__device__ __align__(16) float   g_d1t[ROWS * HH];

// ---------------- packed f32x2 helpers ------------------------------------------
static __device__ __forceinline__ ull fma2(ull a, ull b, ull c) {
    ull r;
    asm("fma.rn.f32x2 %0, %1, %2, %3;" : "=l"(r) : "l"(a), "l"(b), "l"(c));
    return r;
}
static __device__ __forceinline__ ull mul2(ull a, ull b) {
    ull r;
    asm("mul.rn.f32x2 %0, %1, %2;" : "=l"(r) : "l"(a), "l"(b));
    return r;
}
static __device__ __forceinline__ ull pk2(float x, float y) {
    ull r;
    asm("mov.b64 %0, {%1, %2};" : "=l"(r) : "f"(x), "f"(y));
    return r;
}
static __device__ __forceinline__ void upk2(ull v, float& x, float& y) {
    asm("mov.b64 {%0, %1}, %2;" : "=f"(x), "=f"(y) : "l"(v));
}

// ---------------- kernel 1: compact adjacency rows into neighbor lists ----------
__global__ void __launch_bounds__(256) k_build_nbr(const float* __restrict__ adj) {
    const int row  = (blockIdx.x << 3) + (threadIdx.x >> 5);
    const int lane = threadIdx.x & 31;
    const int i    = row & (NN - 1);
    const float* arow = adj + ((size_t)row << 9);
    int16_t* outp = g_nbr + ((size_t)row << 9);
    int off = 0;
    #pragma unroll
    for (int base = 0; base < NN; base += 32) {
        const int j = base + lane;
        const bool p = (arow[j] != 0.f) || (j == i);   // diag forced to 1
        const unsigned msk = __ballot_sync(0xffffffffu, p);
        if (p) outp[off + __popc(msk & ((1u << lane) - 1u))] = (int16_t)j;
        off += __popc(msk);
    }
    if (lane == 0) g_cnt[row] = off;
}

// ---------------- kernel 2: GEMM  C[M,64] = A[M,K] @ B[K,64]  -------------------
template<int K, int LAYER>
__global__ void __launch_bounds__(256) k_gemm(const float* __restrict__ Aext,
                                              const float* __restrict__ Bw) {
    const float* __restrict__ A = (LAYER == 0) ? Aext : g_x1;
    float* __restrict__ C = (LAYER == 0) ? g_hp0 : g_hp1;
    __shared__ float As[32][72];   // As[kk][m] (transposed)
    __shared__ float Bs[32][72];   // Bs[kk][n]
    const int bm = blockIdx.x << 6;
    const int t  = threadIdx.x;
    const int ty = t >> 4, tx = t & 15;
    ull acc[4][2];
    #pragma unroll
    for (int r = 0; r < 4; r++) { acc[r][0] = 0ull; acc[r][1] = 0ull; }

    for (int k0 = 0; k0 < K; k0 += 32) {
        #pragma unroll
        for (int l = 0; l < 2; l++) {
            const int idx = t + (l << 8);          // 0..511
            const int m  = idx >> 3;
            const int kq = (idx & 7) << 2;
            float4 av = *(const float4*)(A + (size_t)(bm + m) * K + k0 + kq);
            As[kq + 0][m] = av.x; As[kq + 1][m] = av.y;
            As[kq + 2][m] = av.z; As[kq + 3][m] = av.w;
            const int kk = idx >> 4;
            const int nq = (idx & 15) << 2;
            *(float4*)&Bs[kk][nq] = *(const float4*)(Bw + (size_t)(k0 + kk) * 64 + nq);
        }
        __syncthreads();
        #pragma unroll
        for (int kk = 0; kk < 32; kk++) {
            const float4 a = *(const float4*)&As[kk][ty << 2];
            const longlong2 bv = *(const longlong2*)&Bs[kk][tx << 2];
            const ull b0 = (ull)bv.x;
            const ull b1 = (ull)bv.y;
            const ull a0 = pk2(a.x, a.x), a1 = pk2(a.y, a.y);
            const ull a2 = pk2(a.z, a.z), a3 = pk2(a.w, a.w);
            acc[0][0] = fma2(a0, b0, acc[0][0]); acc[0][1] = fma2(a0, b1, acc[0][1]);
            acc[1][0] = fma2(a1, b0, acc[1][0]); acc[1][1] = fma2(a1, b1, acc[1][1]);
            acc[2][0] = fma2(a2, b0, acc[2][0]); acc[2][1] = fma2(a2, b1, acc[2][1]);
            acc[3][0] = fma2(a3, b0, acc[3][0]); acc[3][1] = fma2(a3, b1, acc[3][1]);
        }
        __syncthreads();
    }
    #pragma unroll
    for (int r = 0; r < 4; r++) {
        float o0, o1, o2, o3;
        upk2(acc[r][0], o0, o1); upk2(acc[r][1], o2, o3);
        *(float4*)(C + (size_t)(bm + (ty << 2) + r) * 64 + (tx << 2)) =
            make_float4(o0, o1, o2, o3);
    }
}

// ---------------- kernel 3: s/d projections, stored NODE-MAJOR [row][h] ---------
template<int LAYER>
__global__ void __launch_bounds__(256) k_sd(const float* __restrict__ asrc,
                                            const float* __restrict__ adst) {
    const float* __restrict__ hp = (LAYER == 0) ? g_hp0 : g_hp1;
    float* __restrict__ s = (LAYER == 0) ? g_s0t : g_s1t;
    float* __restrict__ d = (LAYER == 0) ? g_d0t : g_d1t;
    const int row  = (blockIdx.x << 3) + (threadIdx.x >> 5);
    const int lane = threadIdx.x & 31;
    const float h0 = hp[(size_t)row * 64 + lane];
    const float h1 = hp[(size_t)row * 64 + 32 + lane];
    float ps[8], pd[8];
    #pragma unroll
    for (int h = 0; h < 8; h++) {
        ps[h] = h0 * asrc[(lane << 3) + h] + h1 * asrc[((lane + 32) << 3) + h];
        pd[h] = h0 * adst[(lane << 3) + h] + h1 * adst[((lane + 32) << 3) + h];
    }
    #pragma unroll
    for (int h = 0; h < 8; h++) {
        #pragma unroll
        for (int o = 16; o; o >>= 1) {
            ps[h] += __shfl_xor_sync(0xffffffffu, ps[h], o);
            pd[h] += __shfl_xor_sync(0xffffffffu, pd[h], o);
        }
    }
    if (lane == 0) {
        *(float4*)(s + (row << 3))     = make_float4(ps[0], ps[1], ps[2], ps[3]);
        *(float4*)(s + (row << 3) + 4) = make_float4(ps[4], ps[5], ps[6], ps[7]);
        *(float4*)(d + (row << 3))     = make_float4(pd[0], pd[1], pd[2], pd[3]);
        *(float4*)(d + (row << 3) + 4) = make_float4(pd[4], pd[5], pd[6], pd[7]);
    }
}

// ---------------- kernel 4: layer-1 ONE-PASS aggregate (no max-subtraction) -----
// wt = exp(leaky(s+d)) [0 if masked]; acc += wt*hp; Z per-lane; normalize at end.
__global__ void __launch_bounds__(128) k_agg1() {
    __shared__ __align__(16) float2 s_w[4][32][8];   // chunk weights, pre-dup {w,w}
    __shared__ int s_off[4][32];                     // chunk hp byte offsets (j<<8)
    const int w = threadIdx.x >> 5, lane = threadIdx.x & 31;
    const int row = (blockIdx.x << 2) + w;
    const int b = row >> 9, i = row & (NN - 1);
    const int cnt = g_cnt[row];
    const int16_t* __restrict__ nbrrow = g_nbr + ((size_t)row << 9);
    const float* __restrict__ dtb = g_d0t + ((size_t)b << 12);   // [i][h]
    const char*  __restrict__ hpl =
        (const char*)(g_hp0 + ((size_t)b << 15)) + (lane << 3);  // lane's 8B in row

    float sh[8], Zl[8];
    {
        const float4 s0 = *(const float4*)(g_s0t + (row << 3));
        const float4 s1 = *(const float4*)(g_s0t + (row << 3) + 4);
        sh[0] = s0.x; sh[1] = s0.y; sh[2] = s0.z; sh[3] = s0.w;
        sh[4] = s1.x; sh[5] = s1.y; sh[6] = s1.z; sh[7] = s1.w;
    }
    ull acc[8];
    #pragma unroll
    for (int h = 0; h < 8; h++) { Zl[h] = 0.f; acc[h] = 0ull; }

    for (int base = 0; base < cnt; base += 32) {
        const int nc = min(32, cnt - base);
        // weight phase: lane <-> neighbor
        float wt[8];
        #pragma unroll
        for (int h = 0; h < 8; h++) wt[h] = 0.f;
        int off = i << 8;                              // valid pad address
        if (lane < nc) {
            const int j = (int)nbrrow[base + lane];
            off = j << 8;
            const float4 da = *(const float4*)(dtb + (j << 3));
            const float4 db = *(const float4*)(dtb + (j << 3) + 4);
            float dv[8] = {da.x, da.y, da.z, da.w, db.x, db.y, db.z, db.w};
            #pragma unroll
            for (int h = 0; h < 8; h++) {
                const float ev = sh[h] + dv[h];
                const float lv = ev >= 0.f ? ev : 0.2f * ev;
                const float e  = (lv != 0.f) ? __expf(lv) : 0.f;
                wt[h] = e;
                Zl[h] += e;
            }
        }
        s_off[w][lane] = off;
        {
            float4* wp = (float4*)&s_w[w][lane][0];
            wp[0] = make_float4(wt[0], wt[0], wt[1], wt[1]);
            wp[1] = make_float4(wt[2], wt[2], wt[3], wt[3]);
            wp[2] = make_float4(wt[4], wt[4], wt[5], wt[5]);
            wp[3] = make_float4(wt[6], wt[6], wt[7], wt[7]);
        }
        __syncwarp();
        // FMA phase: groups of 8 with batched loads (MLP=8)
        for (int g = 0; g < nc; g += 8) {
            ull hpv[8];
            #pragma unroll
            for (int q = 0; q < 8; q++)
                hpv[q] = *(const ull*)(hpl + s_off[w][g + q]);
            #pragma unroll
            for (int q = 0; q < 8; q++) {
                const longlong2* wp2 = (const longlong2*)&s_w[w][g + q][0];
                const longlong2 w01 = wp2[0], w23 = wp2[1];
                const longlong2 w45 = wp2[2], w67 = wp2[3];
                acc[0] = fma2((ull)w01.x, hpv[q], acc[0]);
                acc[1] = fma2((ull)w01.y, hpv[q], acc[1]);
                acc[2] = fma2((ull)w23.x, hpv[q], acc[2]);
                acc[3] = fma2((ull)w23.y, hpv[q], acc[3]);
                acc[4] = fma2((ull)w45.x, hpv[q], acc[4]);
                acc[5] = fma2((ull)w45.y, hpv[q], acc[5]);
                acc[6] = fma2((ull)w67.x, hpv[q], acc[6]);
                acc[7] = fma2((ull)w67.y, hpv[q], acc[7]);
            }
        }
        __syncwarp();
    }
    // combine per-lane Z, normalize, elu, store
    #pragma unroll
    for (int h = 0; h < 8; h++)
        #pragma unroll
        for (int o = 16; o; o >>= 1)
            Zl[h] += __shfl_xor_sync(0xffffffffu, Zl[h], o);
    float* xout = g_x1 + ((size_t)row << 9);
    #pragma unroll
    for (int h = 0; h < 8; h++) {
        const float rz = 1.f / Zl[h];
        float xf, yf; upk2(mul2(acc[h], pk2(rz, rz)), xf, yf);
        xf = xf > 0.f ? xf : expm1f(xf);
        yf = yf > 0.f ? yf : expm1f(yf);
        ((float2*)(xout + (h << 6)))[lane] = make_float2(xf, yf);
    }
}

// ---------------- kernel 5: layer-2 two-pass (Z sweep, then scalar-weight FMA) --
__global__ void __launch_bounds__(128) k_agg2(float* __restrict__ out) {
    __shared__ __align__(16) float2 s_wb[4][32];
    __shared__ int s_off[4][32];
    const int w = threadIdx.x >> 5, lane = threadIdx.x & 31;
    const int row = (blockIdx.x << 2) + w;
    const int b = row >> 9, i = row & (NN - 1);
    const int cnt = g_cnt[row];
    const int16_t* __restrict__ nbrrow = g_nbr + ((size_t)row << 9);
    const float* __restrict__ dtb = g_d1t + ((size_t)b << 12);
    const char*  __restrict__ hpl =
        (const char*)(g_hp1 + ((size_t)b << 15)) + (lane << 3);

    float sh[8], Zl[8];
    {
        const float4 s0 = *(const float4*)(g_s1t + (row << 3));
        const float4 s1 = *(const float4*)(g_s1t + (row << 3) + 4);
        sh[0] = s0.x; sh[1] = s0.y; sh[2] = s0.z; sh[3] = s0.w;
        sh[4] = s1.x; sh[5] = s1.y; sh[6] = s1.z; sh[7] = s1.w;
    }
    #pragma unroll
    for (int h = 0; h < 8; h++) Zl[h] = 0.f;

    // pass 1: per-lane Z over strided neighbors
    for (int p = lane; p < cnt; p += 32) {
        const int j = (int)nbrrow[p];
        const float4 da = *(const float4*)(dtb + (j << 3));
        const float4 db = *(const float4*)(dtb + (j << 3) + 4);
        float dv[8] = {da.x, da.y, da.z, da.w, db.x, db.y, db.z, db.w};
        #pragma unroll
        for (int h = 0; h < 8; h++) {
            const float ev = sh[h] + dv[h];
            const float lv = ev >= 0.f ? ev : 0.2f * ev;
            if (lv != 0.f) Zl[h] += __expf(lv);
        }
    }
    #pragma unroll
    for (int h = 0; h < 8; h++)
        #pragma unroll
        for (int o = 16; o; o >>= 1)
            Zl[h] += __shfl_xor_sync(0xffffffffu, Zl[h], o);
    float rz8[8];
    #pragma unroll
    for (int h = 0; h < 8; h++) rz8[h] = 0.125f / Zl[h];

    // pass 2: scalar weights (head-mean folded) + FMA
    ull acc = 0ull;
    for (int base = 0; base < cnt; base += 32) {
        const int nc = min(32, cnt - base);
        float ws = 0.f;
        int off = i << 8;
        if (lane < nc) {
            const int j = (int)nbrrow[base + lane];
            off = j << 8;
            const float4 da = *(const float4*)(dtb + (j << 3));
            const float4 db = *(const float4*)(dtb + (j << 3) + 4);
            float dv[8] = {da.x, da.y, da.z, da.w, db.x, db.y, db.z, db.w};
            #pragma unroll
            for (int h = 0; h < 8; h++) {
                const float ev = sh[h] + dv[h];
                const float lv = ev >= 0.f ? ev : 0.2f * ev;
                if (lv != 0.f) ws += __expf(lv) * rz8[h];
            }
        }
        s_off[w][lane] = off;
        s_wb[w][lane] = make_float2(ws, ws);
        __syncwarp();
        for (int g = 0; g < nc; g += 8) {
            ull hpv[8];
            #pragma unroll
            for (int q = 0; q < 8; q++)
                hpv[q] = *(const ull*)(hpl + s_off[w][g + q]);
            #pragma unroll
            for (int q = 0; q < 8; q++)
                acc = fma2(*(const ull*)&s_wb[w][g + q], hpv[q], acc);
        }
        __syncwarp();
    }
    float xf, yf; upk2(acc, xf, yf);
    ((float2*)(out + ((size_t)row << 6)))[lane] = make_float2(xf, yf);
}

// ---------------- launch --------------------------------------------------------
extern "C" void kernel_launch(void* const* d_in, const int* in_sizes, int n_in,
                              void* d_out, int out_size) {
    const float* x     = (const float*)d_in[0];
    const float* adj   = (const float*)d_in[1];
    const float* W0    = (const float*)d_in[4];
    const float* asrc0 = (const float*)d_in[5];
    const float* adst0 = (const float*)d_in[6];
    const float* W1    = (const float*)d_in[7];
    const float* asrc1 = (const float*)d_in[8];
    const float* adst1 = (const float*)d_in[9];
    float* out = (float*)d_out;

    k_build_nbr<<<ROWS / 8, 256>>>(adj);
    k_gemm<64, 0><<<ROWS / 64, 256>>>(x, W0);
    k_sd<0><<<ROWS / 8, 256>>>(asrc0, adst0);
    k_agg1<<<ROWS / 4, 128>>>();
    k_gemm<512, 1><<<ROWS / 64, 256>>>(nullptr, W1);
    k_sd<1><<<ROWS / 8, 256>>>(asrc1, adst1);
    k_agg2<<<ROWS / 4, 128>>>(out);
}